// round 1
// baseline (speedup 1.0000x reference)
#include <cuda_runtime.h>
#include <cstdint>

#define T_STEPS 2048
#define BATCH   64
#define H       256
#define HHALF   128
#define TBH     (T_STEPS * BATCH * H)

// Scratch (no cudaMalloc allowed): transposed W_ih and precomputed xproj.
__device__ float g_Wt[H * H];                      // Wt[i][h] = W_ih[h][i]
__device__ float g_xproj[(size_t)TBH];             // [T*B][H]

// ---------------------------------------------------------------------------
// Kernel 1: transpose W_ih (256x256). Trivial cost.
// ---------------------------------------------------------------------------
__global__ void transpose_kernel(const float* __restrict__ W, float* __restrict__ Wt)
{
    __shared__ float tile[32][33];
    const int bx = blockIdx.x & 7;        // 8 tiles along i
    const int by = blockIdx.x >> 3;       // 8 tiles along h
    const int x0 = bx * 32, y0 = by * 32;
    tile[threadIdx.y][threadIdx.x] = W[(y0 + threadIdx.y) * H + (x0 + threadIdx.x)];
    __syncthreads();
    Wt[(x0 + threadIdx.y) * H + (y0 + threadIdx.x)] = tile[threadIdx.x][threadIdx.y];
}

// ---------------------------------------------------------------------------
// Kernel 2: xproj[r][h] = sum_i x[r][i] * Wt[i][h] + (b_ih[h] + b_hh[h])
// 32 rows per block, 256 threads. Thread tile: 8 rows x 4 cols (float4).
// ---------------------------------------------------------------------------
__global__ __launch_bounds__(256, 2)
void xproj_kernel(const float* __restrict__ x, const float* __restrict__ Wt,
                  const float* __restrict__ b_ih, const float* __restrict__ b_hh,
                  float* __restrict__ xproj)
{
    __shared__ __align__(16) float4 xs[32][64];    // 32 rows x 256 floats

    const int tid  = threadIdx.x;
    const size_t row0 = (size_t)blockIdx.x * 32;

    // Stage x tile (32*256 floats = 2048 float4, 8 per thread)
    const float4* xg = reinterpret_cast<const float4*>(x + row0 * H);
    float4* xs_flat = &xs[0][0];
    #pragma unroll
    for (int i = 0; i < 8; i++) {
        int idx = tid + i * 256;
        xs_flat[idx] = xg[idx];
    }
    __syncthreads();

    const int xc = tid & 63;      // column group: cols c0..c0+3
    const int rg = tid >> 6;      // row group: rows m0..m0+7
    const int c0 = 4 * xc;
    const int m0 = 8 * rg;

    float acc[8][4];
    #pragma unroll
    for (int m = 0; m < 8; m++)
        #pragma unroll
        for (int j = 0; j < 4; j++) acc[m][j] = 0.0f;

    const float4* WtB = reinterpret_cast<const float4*>(Wt) + xc;  // Wt[k][c0]

    #pragma unroll 4
    for (int k4 = 0; k4 < 64; k4++) {
        float4 w0 = __ldg(&WtB[(4 * k4 + 0) * 64]);
        float4 w1 = __ldg(&WtB[(4 * k4 + 1) * 64]);
        float4 w2 = __ldg(&WtB[(4 * k4 + 2) * 64]);
        float4 w3 = __ldg(&WtB[(4 * k4 + 3) * 64]);
        #pragma unroll
        for (int mm = 0; mm < 8; mm++) {
            float4 xv = xs[m0 + mm][k4];
            acc[mm][0] = fmaf(xv.x, w0.x, acc[mm][0]);
            acc[mm][0] = fmaf(xv.y, w1.x, acc[mm][0]);
            acc[mm][0] = fmaf(xv.z, w2.x, acc[mm][0]);
            acc[mm][0] = fmaf(xv.w, w3.x, acc[mm][0]);

            acc[mm][1] = fmaf(xv.x, w0.y, acc[mm][1]);
            acc[mm][1] = fmaf(xv.y, w1.y, acc[mm][1]);
            acc[mm][1] = fmaf(xv.z, w2.y, acc[mm][1]);
            acc[mm][1] = fmaf(xv.w, w3.y, acc[mm][1]);

            acc[mm][2] = fmaf(xv.x, w0.z, acc[mm][2]);
            acc[mm][2] = fmaf(xv.y, w1.z, acc[mm][2]);
            acc[mm][2] = fmaf(xv.z, w2.z, acc[mm][2]);
            acc[mm][2] = fmaf(xv.w, w3.z, acc[mm][2]);

            acc[mm][3] = fmaf(xv.x, w0.w, acc[mm][3]);
            acc[mm][3] = fmaf(xv.y, w1.w, acc[mm][3]);
            acc[mm][3] = fmaf(xv.z, w2.w, acc[mm][3]);
            acc[mm][3] = fmaf(xv.w, w3.w, acc[mm][3]);
        }
    }

    float4 bias;
    bias.x = b_ih[c0 + 0] + b_hh[c0 + 0];
    bias.y = b_ih[c0 + 1] + b_hh[c0 + 1];
    bias.z = b_ih[c0 + 2] + b_hh[c0 + 2];
    bias.w = b_ih[c0 + 3] + b_hh[c0 + 3];

    #pragma unroll
    for (int mm = 0; mm < 8; mm++) {
        float4 o;
        o.x = acc[mm][0] + bias.x;
        o.y = acc[mm][1] + bias.y;
        o.z = acc[mm][2] + bias.z;
        o.w = acc[mm][3] + bias.w;
        reinterpret_cast<float4*>(xproj + (row0 + m0 + mm) * H + c0)[0] = o;
    }
}

// ---------------------------------------------------------------------------
// Kernel 3: sequential scan. One 2-CTA cluster per batch row.
// Each CTA owns 128 output columns; its 128x256 W_hh slice lives in registers
// (128 regs/thread, 256 threads). h (256 floats) replicated in smem, double
// buffered; halves exchanged via DSMEM store + barrier.cluster each step.
// ---------------------------------------------------------------------------
__device__ __forceinline__ uint32_t smem_u32(const void* p)
{
    uint32_t a;
    asm("{ .reg .u64 t; cvta.to.shared.u64 t, %1; cvt.u32.u64 %0, t; }"
        : "=r"(a) : "l"(p));
    return a;
}

__global__ void __cluster_dims__(2, 1, 1) __launch_bounds__(256, 1)
rnn_scan_kernel(const float* __restrict__ xproj, const float* __restrict__ hx,
                const float* __restrict__ W_hh, float* __restrict__ out,
                float* __restrict__ hlast)
{
    __shared__ __align__(16) float h_s[2][H];     // double-buffered hidden state
    __shared__ float part[8][HHALF];              // k-split partial sums

    const int tid = threadIdx.x;
    uint32_t rank;
    asm("mov.u32 %0, %%cluster_ctarank;" : "=r"(rank));
    const int b  = blockIdx.x >> 1;
    const int j0 = (int)rank * HHALF;             // this CTA's output column base

    const int c  = tid & 31;                      // column group (4 cols)
    const int s  = tid >> 5;                      // warp id = k-split (32 k's)
    const int jl = 4 * c;

    // --- load W_hh slice into registers: w[jj][kk] = W_hh[j0+jl+jj][32s+kk]
    float w0[32], w1[32], w2[32], w3[32];
    {
        const float* Wb = W_hh + (size_t)(j0 + jl) * H + 32 * s;
        #pragma unroll
        for (int kk = 0; kk < 32; kk++) {
            w0[kk] = Wb[kk];
            w1[kk] = Wb[H + kk];
            w2[kk] = Wb[2 * H + kk];
            w3[kk] = Wb[3 * H + kk];
        }
    }

    // --- init hidden state (each CTA keeps the full vector locally)
    h_s[0][tid] = hx[(size_t)b * H + tid];

    // --- DSMEM addresses for writing my half into the peer's h buffers
    uint32_t peerAddr0 = 0, peerAddr1 = 0;
    if (tid < HHALF) {
        uint32_t la0 = smem_u32(&h_s[0][j0 + tid]);
        uint32_t la1 = smem_u32(&h_s[1][j0 + tid]);
        uint32_t pr = rank ^ 1u;
        asm("mapa.shared::cluster.u32 %0, %1, %2;" : "=r"(peerAddr0) : "r"(la0), "r"(pr));
        asm("mapa.shared::cluster.u32 %0, %1, %2;" : "=r"(peerAddr1) : "r"(la1), "r"(pr));
    }
    __syncthreads();

    int cur = 0;
    for (int t = 0; t < T_STEPS; t++) {
        // prefetch this step's xproj early; latency hidden by FMA loop
        float xp = 0.0f;
        if (tid < HHALF)
            xp = __ldg(xproj + (size_t)t * BATCH * H + (size_t)b * H + j0 + tid);

        // --- mat-vec partials: 4 cols x 32 k's per thread
        const float4* h4 = reinterpret_cast<const float4*>(&h_s[cur][32 * s]);
        float a0 = 0.f, a1 = 0.f, a2 = 0.f, a3 = 0.f;
        #pragma unroll
        for (int q = 0; q < 8; q++) {
            float4 hv = h4[q];
            a0 = fmaf(w0[4*q+0], hv.x, a0); a0 = fmaf(w0[4*q+1], hv.y, a0);
            a0 = fmaf(w0[4*q+2], hv.z, a0); a0 = fmaf(w0[4*q+3], hv.w, a0);
            a1 = fmaf(w1[4*q+0], hv.x, a1); a1 = fmaf(w1[4*q+1], hv.y, a1);
            a1 = fmaf(w1[4*q+2], hv.z, a1); a1 = fmaf(w1[4*q+3], hv.w, a1);
            a2 = fmaf(w2[4*q+0], hv.x, a2); a2 = fmaf(w2[4*q+1], hv.y, a2);
            a2 = fmaf(w2[4*q+2], hv.z, a2); a2 = fmaf(w2[4*q+3], hv.w, a2);
            a3 = fmaf(w3[4*q+0], hv.x, a3); a3 = fmaf(w3[4*q+1], hv.y, a3);
            a3 = fmaf(w3[4*q+2], hv.z, a3); a3 = fmaf(w3[4*q+3], hv.w, a3);
        }
        part[s][jl + 0] = a0;
        part[s][jl + 1] = a1;
        part[s][jl + 2] = a2;
        part[s][jl + 3] = a3;
        __syncthreads();

        const int nxt = cur ^ 1;
        if (tid < HHALF) {
            float v = part[0][tid] + part[1][tid] + part[2][tid] + part[3][tid]
                    + part[4][tid] + part[5][tid] + part[6][tid] + part[7][tid] + xp;
            float hn = tanhf(v);

            out[(size_t)t * BATCH * H + (size_t)b * H + j0 + tid] = hn;
            if (hlast && t == T_STEPS - 1)
                hlast[(size_t)b * H + j0 + tid] = hn;

            h_s[nxt][j0 + tid] = hn;                       // my local copy
            uint32_t pa = nxt ? peerAddr1 : peerAddr0;     // peer's copy
            asm volatile("st.shared::cluster.f32 [%0], %1;" :: "r"(pa), "f"(hn) : "memory");
        }

        // cluster barrier: release my DSMEM writes, acquire peer's
        asm volatile("barrier.cluster.arrive.aligned;" ::: "memory");
        asm volatile("barrier.cluster.wait.aligned;"   ::: "memory");
        cur = nxt;
    }
}

// ---------------------------------------------------------------------------
extern "C" void kernel_launch(void* const* d_in, const int* in_sizes, int n_in,
                              void* d_out, int out_size)
{
    const float* x    = (const float*)d_in[0];   // [T,B,256]
    const float* hx   = (const float*)d_in[1];   // [B,256]
    const float* W_ih = (const float*)d_in[2];   // [256,256]
    const float* W_hh = (const float*)d_in[3];   // [256,256]
    const float* b_ih = (const float*)d_in[4];   // [256]
    const float* b_hh = (const float*)d_in[5];   // [256]
    float* out = (float*)d_out;

    float* d_Wt;
    float* d_xproj;
    cudaGetSymbolAddress((void**)&d_Wt, g_Wt);
    cudaGetSymbolAddress((void**)&d_xproj, g_xproj);

    // h_last tail only if the output buffer has room for it
    float* hlast = (out_size >= TBH + BATCH * H) ? (out + TBH) : nullptr;

    transpose_kernel<<<64, dim3(32, 32)>>>(W_ih, d_Wt);
    xproj_kernel<<<(T_STEPS * BATCH) / 32, 256>>>(x, d_Wt, b_ih, b_hh, d_xproj);
    rnn_scan_kernel<<<2 * BATCH, 256>>>(d_xproj, hx, W_hh, out, hlast);
    (void)in_sizes; (void)n_in;
}